// round 5
// baseline (speedup 1.0000x reference)
#include <cuda_runtime.h>
#include <cuda_bf16.h>
#include <cstdint>
#include <cstddef>

#define BB   2
#define HH   8
#define LL   4096
#define DKK  128
#define DVV  128
#define CC   32
#define NCH  128
#define BHT  16
#define SDK  132

#define OUT_ELEMS  ((size_t)BB * HH * LL * DVV)
#define S_ELEMS    ((size_t)BB * HH * DKK * DVV)

typedef unsigned long long ull;

// ---------------- scratch (device globals) ----------------
// g_wqT: [bh][ch][128][64] k-major, cols = [w rows 0..31 | q rows 32..63],
//        column-swizzled: phys_col = col ^ (((r>>5)&3)<<4)
// g_kR : [bh][ch][32][128] k-hat row-major
// g_at2: [bh][ch][32][32]  masked attn, plain row-major
// g_u2 : [bh][slice8][ch][32][16] u blocked per dv-slice
__device__ float g_wqT[(size_t)BHT * NCH * 128 * 64];
__device__ float g_kR [(size_t)BHT * NCH * 32 * 128];
__device__ float g_at2[(size_t)BHT * NCH * 32 * 32];
__device__ float g_u2 [(size_t)BHT * 8 * NCH * 32 * 16];

__device__ __forceinline__ float dot4(float4 a, float4 b) {
    return a.x * b.x + a.y * b.y + a.z * b.z + a.w * b.w;
}
__device__ __forceinline__ void fma4(float4& acc, float a, float4 b) {
    acc.x += a * b.x; acc.y += a * b.y; acc.z += a * b.z; acc.w += a * b.w;
}
__device__ __forceinline__ ull pk1(float x) {
    ull r; asm("mov.b64 %0,{%1,%1};" : "=l"(r) : "f"(x)); return r;
}
__device__ __forceinline__ void fm2(ull& a, ull b, ull c) {
    asm("fma.rn.f32x2 %0,%1,%2,%3;" : "=l"(a) : "l"(b), "l"(c), "l"(a));
}
__device__ __forceinline__ ull ad2r(ull a, ull b) {
    ull r; asm("add.rn.f32x2 %0,%1,%2;" : "=l"(r) : "l"(a), "l"(b)); return r;
}
__device__ __forceinline__ float2 upk(ull a) {
    float2 f; asm("mov.b64 {%0,%1},%2;" : "=f"(f.x), "=f"(f.y) : "l"(a)); return f;
}
__device__ __forceinline__ uint32_t s2u(const void* p) {
    return (uint32_t)__cvta_generic_to_shared(p);
}
__device__ __forceinline__ void mbar_init(uint32_t mbar, uint32_t cnt) {
    asm volatile("mbarrier.init.shared.b64 [%0], %1;" :: "r"(mbar), "r"(cnt) : "memory");
}
__device__ __forceinline__ void mbar_expect(uint32_t mbar, uint32_t bytes) {
    asm volatile("mbarrier.arrive.expect_tx.shared.b64 _, [%0], %1;" :: "r"(mbar), "r"(bytes) : "memory");
}
__device__ __forceinline__ void mbar_wait(uint32_t mbar, uint32_t parity) {
    asm volatile(
        "{\n\t.reg .pred P;\n\t"
        "W%=:\n\t"
        "mbarrier.try_wait.parity.acquire.cta.shared::cta.b64 P, [%0], %1, 0x989680;\n\t"
        "@P bra D%=;\n\t"
        "bra W%=;\n\t"
        "D%=:\n\t}"
        :: "r"(mbar), "r"(parity) : "memory");
}
__device__ __forceinline__ void bulkcp(uint32_t dst, const void* src, uint32_t bytes, uint32_t mbar) {
    asm volatile("cp.async.bulk.shared::cta.global.mbarrier::complete_tx::bytes [%0], [%1], %2, [%3];"
        :: "r"(dst), "l"(src), "r"(bytes), "r"(mbar) : "memory");
}

// =====================================================================
// Phase 1: per-chunk parallel — l2norm, tri-inverse, u, w, attn
// grid (NCH, BHT), 256 threads
// =====================================================================
__global__ __launch_bounds__(256) void phase1_kernel(
    const float* __restrict__ gq, const float* __restrict__ gk,
    const float* __restrict__ gv, const float* __restrict__ gbeta)
{
    extern __shared__ float sm[];
    float* sq    = sm;                       // CC*SDK
    float* sk    = sq + CC * SDK;
    float* sv    = sk + CC * SDK;
    float* sA    = sv + CC * SDK;            // CC*(CC+1)
    float* sbeta = sA + CC * (CC + 1);
    float* sqs   = sbeta + CC;
    float* sks   = sqs + CC;

    const int t  = threadIdx.x;
    const int ch = blockIdx.x;
    const int bh = blockIdx.y;
    const size_t gbase = ((size_t)bh * LL + (size_t)ch * CC) * DKK;

    {
        const float4* q4 = (const float4*)(gq + gbase);
        const float4* k4 = (const float4*)(gk + gbase);
        const float4* v4 = (const float4*)(gv + gbase);
        for (int idx = t; idx < CC * DKK / 4; idx += 256) {
            int r = idx >> 5, c4 = idx & 31;
            ((float4*)(sq + r * SDK))[c4] = q4[idx];
            ((float4*)(sk + r * SDK))[c4] = k4[idx];
            ((float4*)(sv + r * SDK))[c4] = v4[idx];
        }
    }
    if (t < CC) sbeta[t] = gbeta[(size_t)bh * LL + (size_t)ch * CC + t];
    __syncthreads();

    // row l2 norms
    {
        int row = t >> 3, seg = t & 7;
        const float4* qr = (const float4*)(sq + row * SDK) + seg * 4;
        const float4* kr = (const float4*)(sk + row * SDK) + seg * 4;
        float s2q = 0.f, s2k = 0.f;
        #pragma unroll
        for (int i2 = 0; i2 < 4; i2++) {
            float4 a = qr[i2]; s2q += dot4(a, a);
            float4 b = kr[i2]; s2k += dot4(b, b);
        }
        #pragma unroll
        for (int off = 4; off; off >>= 1) {
            s2q += __shfl_down_sync(0xffffffffu, s2q, off, 8);
            s2k += __shfl_down_sync(0xffffffffu, s2k, off, 8);
        }
        if (seg == 0) { sqs[row] = rsqrtf(s2q + 1e-6f); sks[row] = rsqrtf(s2k + 1e-6f); }
    }
    __syncthreads();
    {
        int row = t >> 3, seg = t & 7;
        float a = sqs[row], b = sks[row];
        float4* qr = (float4*)(sq + row * SDK) + seg * 4;
        float4* kr = (float4*)(sk + row * SDK) + seg * 4;
        #pragma unroll
        for (int i2 = 0; i2 < 4; i2++) {
            float4 x = qr[i2]; x.x *= a; x.y *= a; x.z *= a; x.w *= a; qr[i2] = x;
            float4 y = kr[i2]; y.x *= b; y.y *= b; y.z *= b; y.w *= b; kr[i2] = y;
        }
    }
    __syncthreads();

    const size_t wqb   = ((size_t)(bh * NCH + ch)) * 8192;
    const size_t krb   = ((size_t)(bh * NCH + ch)) * 4096;
    const size_t abase = ((size_t)(bh * NCH + ch)) * 1024;

    // q-hat (k-major) -> g_wqT logical cols 32..63, swizzled
    {
        int d = t >> 1, half = t & 1, i0q = half * 16;
        int sw = ((d >> 5) & 3) << 4;
        #pragma unroll
        for (int ii = 0; ii < 16; ii += 4) {
            float4 a = make_float4(sq[(i0q + ii) * SDK + d], sq[(i0q + ii + 1) * SDK + d],
                                   sq[(i0q + ii + 2) * SDK + d], sq[(i0q + ii + 3) * SDK + d]);
            *(float4*)(g_wqT + wqb + (size_t)d * 64 + ((32 + i0q + ii) ^ sw)) = a;
        }
    }

    // k-hat row-major -> g_kR
    for (int idx = t; idx < 1024; idx += 256) {
        int r = idx >> 5, c4 = idx & 31;
        *(float4*)(g_kR + krb + (size_t)r * 128 + (c4 << 2)) =
            *(const float4*)(sk + r * SDK + (c4 << 2));
    }

    // dots: A strict-lower; attn lower-incl-diag (plain row-major)
    {
        int ti = t >> 4, tj = t & 15;
        int i0 = 2 * ti, j0 = 2 * tj;
        float dkk00 = 0, dkk01 = 0, dkk10 = 0, dkk11 = 0;
        float dqk00 = 0, dqk01 = 0, dqk10 = 0, dqk11 = 0;
        const float4* ki0 = (const float4*)(sk + i0 * SDK);
        const float4* ki1 = (const float4*)(sk + (i0 + 1) * SDK);
        const float4* kj0 = (const float4*)(sk + j0 * SDK);
        const float4* kj1 = (const float4*)(sk + (j0 + 1) * SDK);
        const float4* qi0 = (const float4*)(sq + i0 * SDK);
        const float4* qi1 = (const float4*)(sq + (i0 + 1) * SDK);
        #pragma unroll 8
        for (int d4 = 0; d4 < 32; d4++) {
            float4 a0 = ki0[d4], a1 = ki1[d4];
            float4 b0 = kj0[d4], b1 = kj1[d4];
            float4 c0 = qi0[d4], c1 = qi1[d4];
            dkk00 += dot4(a0, b0); dkk01 += dot4(a0, b1);
            dkk10 += dot4(a1, b0); dkk11 += dot4(a1, b1);
            dqk00 += dot4(c0, b0); dqk01 += dot4(c0, b1);
            dqk10 += dot4(c1, b0); dqk11 += dot4(c1, b1);
        }
        float bi0 = sbeta[i0], bi1 = sbeta[i0 + 1];
        sA[i0 * (CC + 1) + j0]           = (i0 > j0)         ? -bi0 * dkk00 : 0.f;
        sA[i0 * (CC + 1) + j0 + 1]       = (i0 > j0 + 1)     ? -bi0 * dkk01 : 0.f;
        sA[(i0 + 1) * (CC + 1) + j0]     = (i0 + 1 > j0)     ? -bi1 * dkk10 : 0.f;
        sA[(i0 + 1) * (CC + 1) + j0 + 1] = (i0 + 1 > j0 + 1) ? -bi1 * dkk11 : 0.f;
        g_at2[abase + (size_t)i0 * 32 + j0]           = (i0 >= j0)         ? dqk00 : 0.f;
        g_at2[abase + (size_t)i0 * 32 + j0 + 1]       = (i0 >= j0 + 1)     ? dqk01 : 0.f;
        g_at2[abase + (size_t)(i0 + 1) * 32 + j0]     = (i0 + 1 >= j0)     ? dqk10 : 0.f;
        g_at2[abase + (size_t)(i0 + 1) * 32 + j0 + 1] = (i0 + 1 >= j0 + 1) ? dqk11 : 0.f;
    }
    __syncthreads();

    // forward substitution (exact reference recurrence), warp 0
    if (t < 32) {
        int lane = t;
        for (int i = 1; i < CC; i++) {
            float s = 0.f;
            if (lane < i) {
                for (int kk = lane + 1; kk < i; kk++)
                    s += sA[i * (CC + 1) + kk] * sA[kk * (CC + 1) + lane];
            }
            __syncwarp();
            if (lane < i) sA[i * (CC + 1) + lane] += s;
            __syncwarp();
        }
        sA[lane * (CC + 1) + lane] = 1.0f;
    }
    __syncthreads();

    for (int idx = t; idx < CC * CC; idx += 256) {
        int i = idx >> 5, j = idx & 31;
        sA[i * (CC + 1) + j] *= sbeta[j];
    }
    __syncthreads();

    // u = Abeta @ v (slice-blocked) ; w = Abeta @ k-hat -> g_wqT cols 0..31 swizzled
    {
        int p = t >> 4, dseg = t & 15;
        int i0 = 2 * p, d0 = 8 * dseg;
        float4 u0a = {0,0,0,0}, u0b = {0,0,0,0}, u1a = {0,0,0,0}, u1b = {0,0,0,0};
        float4 w0a = {0,0,0,0}, w0b = {0,0,0,0}, w1a = {0,0,0,0}, w1b = {0,0,0,0};
        #pragma unroll 4
        for (int j = 0; j < CC; j++) {
            float a0 = sA[i0 * (CC + 1) + j];
            float a1 = sA[(i0 + 1) * (CC + 1) + j];
            float4 va = *(const float4*)(sv + j * SDK + d0);
            float4 vb = *(const float4*)(sv + j * SDK + d0 + 4);
            float4 ka = *(const float4*)(sk + j * SDK + d0);
            float4 kb = *(const float4*)(sk + j * SDK + d0 + 4);
            fma4(u0a, a0, va); fma4(u0b, a0, vb);
            fma4(u1a, a1, va); fma4(u1b, a1, vb);
            fma4(w0a, a0, ka); fma4(w0b, a0, kb);
            fma4(w1a, a1, ka); fma4(w1b, a1, kb);
        }
        int sl = d0 >> 4, off = d0 & 15;
        size_t ub2 = (((size_t)(bh * 8 + sl)) * NCH + ch) * 512;
        *(float4*)(g_u2 + ub2 + (size_t)i0 * 16 + off)           = u0a;
        *(float4*)(g_u2 + ub2 + (size_t)i0 * 16 + off + 4)       = u0b;
        *(float4*)(g_u2 + ub2 + (size_t)(i0 + 1) * 16 + off)     = u1a;
        *(float4*)(g_u2 + ub2 + (size_t)(i0 + 1) * 16 + off + 4) = u1b;
        float w0arr[8] = {w0a.x, w0a.y, w0a.z, w0a.w, w0b.x, w0b.y, w0b.z, w0b.w};
        float w1arr[8] = {w1a.x, w1a.y, w1a.z, w1a.w, w1b.x, w1b.y, w1b.z, w1b.w};
        #pragma unroll
        for (int dd = 0; dd < 8; dd++) {
            int d = d0 + dd;
            int sw = ((d >> 5) & 3) << 4;
            *(float2*)(g_wqT + wqb + (size_t)d * 64 + (i0 ^ sw)) =
                make_float2(w0arr[dd], w1arr[dd]);
        }
    }
}

// =====================================================================
// Phase 2: sequential scan, dv split 8x16. grid (8, BHT), 512 threads.
// 2x4 register tiles, k-split-4 + shuffle reduce; swizzled smem.
// buf: wqT 8192 | kR 4096 | at 1024 | u 512  (floats)
// =====================================================================
#define BUF_F   13824
#define OFF_K   8192
#define OFF_AT  12288
#define OFF_U   13312
#define TX_BYTES 55296u

__global__ __launch_bounds__(512) void phase2_kernel(
    float* __restrict__ out, float* __restrict__ Sout)
{
    extern __shared__ float sm[];
    float* sS   = sm + 4;                 // [128][16], cols swizzled ^((r>>5)<<2)
    float* po   = sm + 4 + 2048;          // [32][16] qS partial
    float* bufs = sm + 4 + 2048 + 512;

    const int t = threadIdx.x;
    const int slice = blockIdx.x;
    const int bh    = blockIdx.y;
    const int c0    = slice * 16;

    const int lane = t & 31, warp = t >> 5;        // 16 warps
    const int kg = lane >> 3, tl = lane & 7;
    const int W = warp & 3, tc = warp >> 2;        // tc 0..3
    const int tr = W * 8 + tl;                     // 0..31 row-pair idx
    const int i0 = tr << 1;                        // rows i0, i0+1 of [w;q]
    const int cb4 = tc << 2;
    const int i0sw = i0 ^ (kg << 4);
    const int cbsw = cb4 ^ (kg << 2);

    const uint32_t mb0 = s2u(sm), mb1 = mb0 + 8;

    for (int idx = t; idx < 2048; idx += 512) sS[idx] = 0.f;
    if (t == 0) { mbar_init(mb0, 1); mbar_init(mb1, 1); }
    __syncthreads();

    const size_t cb0 = (size_t)bh * NCH;
    const size_t ublk = ((size_t)(bh * 8 + slice)) * NCH;
    if (t == 0) {
        mbar_expect(mb0, TX_BYTES);
        bulkcp(s2u(bufs),           g_wqT + cb0 * 8192, 32768, mb0);
        bulkcp(s2u(bufs + OFF_K),   g_kR  + cb0 * 4096, 16384, mb0);
        bulkcp(s2u(bufs + OFF_AT),  g_at2 + cb0 * 1024, 4096, mb0);
        bulkcp(s2u(bufs + OFF_U),   g_u2  + ublk * 512, 2048, mb0);
    }

    // second-half thread roles
    const int rp  = t & 63;             // S-update: rows rp, rp+64 (threads 0..255: rp = t>>2? see below)
    (void)rp;

    for (int ch = 0; ch < NCH; ch++) {
        const int b = ch & 1;
        float* B  = bufs + b * BUF_F;
        float* bu = B + OFF_U;

        __syncthreads();
        if (t == 0 && ch + 1 < NCH) {
            uint32_t mb = b ? mb0 : mb1;
            float* B2 = bufs + (b ^ 1) * BUF_F;
            const size_t cb = cb0 + ch + 1;
            mbar_expect(mb, TX_BYTES);
            bulkcp(s2u(B2),          g_wqT + cb * 8192, 32768, mb);
            bulkcp(s2u(B2 + OFF_K),  g_kR  + cb * 4096, 16384, mb);
            bulkcp(s2u(B2 + OFF_AT), g_at2 + cb * 1024, 4096, mb);
            bulkcp(s2u(B2 + OFF_U),  g_u2  + (ublk + ch + 1) * 512, 2048, mb);
        }
        mbar_wait(b ? mb1 : mb0, (ch >> 1) & 1);

        // ---- P = [w;q]@S : 2 rows x 4 cols, k-split-4 ----
        ull a00 = 0, a01 = 0, a10 = 0, a11 = 0;
        {
            const float* wp = B + (kg << 5) * 64 + i0sw;
            const float* sp = sS + (kg << 5) * 16 + cbsw;
            #pragma unroll 8
            for (int k = 0; k < 32; k++) {
                float2 w2 = *(const float2*)wp;
                ulonglong2 s2 = *(const ulonglong2*)sp;
                fm2(a00, pk1(w2.x), s2.x); fm2(a01, pk1(w2.x), s2.y);
                fm2(a10, pk1(w2.y), s2.x); fm2(a11, pk1(w2.y), s2.y);
                wp += 64; sp += 16;
            }
        }
        #pragma unroll
        for (int m = 8; m <= 16; m <<= 1) {
            a00 = ad2r(a00, __shfl_xor_sync(0xffffffffu, a00, m));
            a01 = ad2r(a01, __shfl_xor_sync(0xffffffffu, a01, m));
            a10 = ad2r(a10, __shfl_xor_sync(0xffffffffu, a10, m));
            a11 = ad2r(a11, __shfl_xor_sync(0xffffffffu, a11, m));
        }
        if (kg == 0) {
            float2 l0 = upk(a00), h0 = upk(a01);
            float2 l1 = upk(a10), h1 = upk(a11);
            if (W < 2) {
                // w-rows: u' = u - wS (rows i0, i0+1 < 32)
                float* up0 = bu + i0 * 16 + cb4;
                float* up1 = bu + (i0 + 1) * 16 + cb4;
                float4 u0 = *(const float4*)up0;
                float4 u1 = *(const float4*)up1;
                u0.x -= l0.x; u0.y -= l0.y; u0.z -= h0.x; u0.w -= h0.y;
                u1.x -= l1.x; u1.y -= l1.y; u1.z -= h1.x; u1.w -= h1.y;
                *(float4*)up0 = u0;
                *(float4*)up1 = u1;
            } else {
                // q-rows: stage qS
                float* pp = po + (i0 - 32) * 16 + cb4;
                *(float4*)(pp)      = make_float4(l0.x, l0.y, h0.x, h0.y);
                *(float4*)(pp + 16) = make_float4(l1.x, l1.y, h1.x, h1.y);
            }
        }
        __syncthreads();

        if (t < 256) {
            // ---- S += kT @ u' : rows r0, r0+64 x 4 cols ----
            const int r0 = t >> 2, ct = t & 3;
            const int cs0 = (ct << 2) ^ ((r0 >> 5) << 2);        // swizzle row r0
            const int cs1 = cs0 ^ 8;                              // row r0+64 (kg+2)
            float* sp0 = sS + r0 * 16 + cs0;
            float* sp1 = sS + (r0 + 64) * 16 + cs1;
            ulonglong2 s0 = *(const ulonglong2*)sp0;
            ulonglong2 s1 = *(const ulonglong2*)sp1;
            const float* kp = B + OFF_K + r0;
            const float* up = bu + (ct << 2);
            #pragma unroll 8
            for (int j = 0; j < 32; j++) {
                float ka = kp[0];
                float kb = kp[64];
                ulonglong2 u2 = *(const ulonglong2*)up;
                fm2(s0.x, pk1(ka), u2.x); fm2(s0.y, pk1(ka), u2.y);
                fm2(s1.x, pk1(kb), u2.x); fm2(s1.y, pk1(kb), u2.y);
                kp += 128; up += 16;
            }
            *(ulonglong2*)sp0 = s0;
            *(ulonglong2*)sp1 = s1;
        } else {
            // ---- o = qS + attn @ u' : 1 row x 2 cols ----
            const int ii2 = (t - 256) >> 3, cp = t & 7;
            ull acc = *(const ull*)(po + ii2 * 16 + (cp << 1));
            const float* atr = B + OFF_AT + ii2 * 32;
            const float* up = bu + (cp << 1);
            #pragma unroll 8
            for (int j = 0; j < 32; j++) {
                fm2(acc, pk1(atr[j]), *(const ull*)(up));
                up += 16;
            }
            float2 f = upk(acc);
            size_t off = ((size_t)bh * LL + (size_t)ch * CC + ii2) * DVV + c0 + (cp << 1);
            *(float2*)(out + off) = f;
        }
    }

    if (Sout != nullptr) {
        __syncthreads();
        size_t sb = (size_t)bh * DKK * DVV;
        for (int idx = t; idx < 2048; idx += 512) {
            int r = idx >> 4, c = idx & 15;
            int csw = c ^ (((r >> 5) & 3) << 2);
            Sout[sb + (size_t)r * DVV + c0 + c] = sS[r * 16 + csw];
        }
    }
}

// =====================================================================
#define P1_SMEM ((3 * CC * SDK + CC * (CC + 1) + 3 * CC) * (int)sizeof(float))
#define P2_SMEM ((4 + 2048 + 512 + 2 * BUF_F) * (int)sizeof(float))

extern "C" void kernel_launch(void* const* d_in, const int* in_sizes, int n_in,
                              void* d_out, int out_size)
{
    const float* q    = (const float*)d_in[0];
    const float* k    = (const float*)d_in[1];
    const float* v    = (const float*)d_in[2];
    const float* beta = (const float*)d_in[3];
    float* out = (float*)d_out;
    float* Sout = ((size_t)out_size >= OUT_ELEMS + S_ELEMS) ? (out + OUT_ELEMS) : nullptr;

    cudaFuncSetAttribute(phase1_kernel, cudaFuncAttributeMaxDynamicSharedMemorySize, P1_SMEM);
    cudaFuncSetAttribute(phase2_kernel, cudaFuncAttributeMaxDynamicSharedMemorySize, P2_SMEM);

    phase1_kernel<<<dim3(NCH, BHT), 256, P1_SMEM>>>(q, k, v, beta);
    phase2_kernel<<<dim3(8, BHT), 512, P2_SMEM>>>(out, Sout);
}

// round 6
// speedup vs baseline: 1.7976x; 1.7976x over previous
#include <cuda_runtime.h>
#include <cuda_bf16.h>
#include <cstdint>
#include <cstddef>

#define BB   2
#define HH   8
#define LL   4096
#define DKK  128
#define DVV  128
#define CC   32
#define NCH  128
#define BHT  16
#define SDK  132

#define OUT_ELEMS  ((size_t)BB * HH * LL * DVV)
#define S_ELEMS    ((size_t)BB * HH * DKK * DVV)

typedef unsigned long long ull;

// ---------------- scratch (device globals) ----------------
// g_wqT: [bh][ch][128][64]  k-major: cols 0..31 = w rows, 32..63 = q-hat rows
// g_kR : [bh][ch][32][128]  k-hat row-major
// g_at2: [bh][ch][32][32]   masked attn, 16B chunks swizzled (j4 ^ (i&7))
// g_u2 : [bh][slice8][ch][32][16] u blocked per dv-slice
__device__ float g_wqT[(size_t)BHT * NCH * 128 * 64];
__device__ float g_kR [(size_t)BHT * NCH * 32 * 128];
__device__ float g_at2[(size_t)BHT * NCH * 32 * 32];
__device__ float g_u2 [(size_t)BHT * 8 * NCH * 32 * 16];

__device__ __forceinline__ float dot4(float4 a, float4 b) {
    return a.x * b.x + a.y * b.y + a.z * b.z + a.w * b.w;
}
__device__ __forceinline__ ull pk1(float x) {
    ull r; asm("mov.b64 %0,{%1,%1};" : "=l"(r) : "f"(x)); return r;
}
__device__ __forceinline__ void fm2(ull& a, ull b, ull c) {
    asm("fma.rn.f32x2 %0,%1,%2,%3;" : "=l"(a) : "l"(b), "l"(c), "l"(a));
}
__device__ __forceinline__ ull ad2r(ull a, ull b) {
    ull r; asm("add.rn.f32x2 %0,%1,%2;" : "=l"(r) : "l"(a), "l"(b)); return r;
}
__device__ __forceinline__ float2 upk(ull a) {
    float2 f; asm("mov.b64 {%0,%1},%2;" : "=f"(f.x), "=f"(f.y) : "l"(a)); return f;
}
__device__ __forceinline__ uint32_t s2u(const void* p) {
    return (uint32_t)__cvta_generic_to_shared(p);
}
__device__ __forceinline__ void mbar_init(uint32_t mbar, uint32_t cnt) {
    asm volatile("mbarrier.init.shared.b64 [%0], %1;" :: "r"(mbar), "r"(cnt) : "memory");
}
__device__ __forceinline__ void mbar_expect(uint32_t mbar, uint32_t bytes) {
    asm volatile("mbarrier.arrive.expect_tx.shared.b64 _, [%0], %1;" :: "r"(mbar), "r"(bytes) : "memory");
}
__device__ __forceinline__ void mbar_wait(uint32_t mbar, uint32_t parity) {
    asm volatile(
        "{\n\t.reg .pred P;\n\t"
        "W%=:\n\t"
        "mbarrier.try_wait.parity.acquire.cta.shared::cta.b64 P, [%0], %1, 0x989680;\n\t"
        "@P bra D%=;\n\t"
        "bra W%=;\n\t"
        "D%=:\n\t}"
        :: "r"(mbar), "r"(parity) : "memory");
}
__device__ __forceinline__ void bulkcp(uint32_t dst, const void* src, uint32_t bytes, uint32_t mbar) {
    asm volatile("cp.async.bulk.shared::cta.global.mbarrier::complete_tx::bytes [%0], [%1], %2, [%3];"
        :: "r"(dst), "l"(src), "r"(bytes), "r"(mbar) : "memory");
}

// =====================================================================
// Phase 1: per-chunk parallel — l2norm, tri-inverse, u, w, attn
// grid (NCH, BHT), 256 threads
// =====================================================================
__global__ __launch_bounds__(256) void phase1_kernel(
    const float* __restrict__ gq, const float* __restrict__ gk,
    const float* __restrict__ gv, const float* __restrict__ gbeta)
{
    extern __shared__ float sm[];
    float* sq    = sm;                       // CC*SDK
    float* sk    = sq + CC * SDK;
    float* sv    = sk + CC * SDK;
    float* sA    = sv + CC * SDK;            // CC*(CC+1)
    float* sbeta = sA + CC * (CC + 1);
    float* sqs   = sbeta + CC;
    float* sks   = sqs + CC;

    const int t  = threadIdx.x;
    const int ch = blockIdx.x;
    const int bh = blockIdx.y;
    const size_t gbase = ((size_t)bh * LL + (size_t)ch * CC) * DKK;

    {
        const float4* q4 = (const float4*)(gq + gbase);
        const float4* k4 = (const float4*)(gk + gbase);
        const float4* v4 = (const float4*)(gv + gbase);
        for (int idx = t; idx < CC * DKK / 4; idx += 256) {
            int r = idx >> 5, c4 = idx & 31;
            ((float4*)(sq + r * SDK))[c4] = q4[idx];
            ((float4*)(sk + r * SDK))[c4] = k4[idx];
            ((float4*)(sv + r * SDK))[c4] = v4[idx];
        }
    }
    if (t < CC) sbeta[t] = gbeta[(size_t)bh * LL + (size_t)ch * CC + t];
    __syncthreads();

    // row l2 norms
    {
        int row = t >> 3, seg = t & 7;
        const float4* qr = (const float4*)(sq + row * SDK) + seg * 4;
        const float4* kr = (const float4*)(sk + row * SDK) + seg * 4;
        float s2q = 0.f, s2k = 0.f;
        #pragma unroll
        for (int i2 = 0; i2 < 4; i2++) {
            float4 a = qr[i2]; s2q += dot4(a, a);
            float4 b = kr[i2]; s2k += dot4(b, b);
        }
        #pragma unroll
        for (int off = 4; off; off >>= 1) {
            s2q += __shfl_down_sync(0xffffffffu, s2q, off, 8);
            s2k += __shfl_down_sync(0xffffffffu, s2k, off, 8);
        }
        if (seg == 0) { sqs[row] = rsqrtf(s2q + 1e-6f); sks[row] = rsqrtf(s2k + 1e-6f); }
    }
    __syncthreads();
    {
        int row = t >> 3, seg = t & 7;
        float a = sqs[row], b = sks[row];
        float4* qr = (float4*)(sq + row * SDK) + seg * 4;
        float4* kr = (float4*)(sk + row * SDK) + seg * 4;
        #pragma unroll
        for (int i2 = 0; i2 < 4; i2++) {
            float4 x = qr[i2]; x.x *= a; x.y *= a; x.z *= a; x.w *= a; qr[i2] = x;
            float4 y = kr[i2]; y.x *= b; y.y *= b; y.z *= b; y.w *= b; kr[i2] = y;
        }
    }
    __syncthreads();

    const size_t wqb   = ((size_t)(bh * NCH + ch)) * 8192;
    const size_t krb   = ((size_t)(bh * NCH + ch)) * 4096;
    const size_t abase = ((size_t)(bh * NCH + ch)) * 1024;

    // q-hat (k-major) -> g_wqT cols 32..63
    {
        int d = t >> 1, half = t & 1, i0q = half * 16;
        #pragma unroll
        for (int ii = 0; ii < 16; ii += 4) {
            float4 a = make_float4(sq[(i0q + ii) * SDK + d], sq[(i0q + ii + 1) * SDK + d],
                                   sq[(i0q + ii + 2) * SDK + d], sq[(i0q + ii + 3) * SDK + d]);
            *(float4*)(g_wqT + wqb + (size_t)d * 64 + 32 + i0q + ii) = a;
        }
    }

    // k-hat row-major -> g_kR
    for (int idx = t; idx < 1024; idx += 256) {
        int r = idx >> 5, c4 = idx & 31;
        *(float4*)(g_kR + krb + (size_t)r * 128 + (c4 << 2)) =
            *(const float4*)(sk + r * SDK + (c4 << 2));
    }

    // dots (f32x2): A strict-lower; attn lower-incl-diag (swizzled)
    {
        int ti = t >> 4, tj = t & 15;
        int i0 = 2 * ti, j0 = 2 * tj;
        ull pkk00 = 0, pkk01 = 0, pkk10 = 0, pkk11 = 0;
        ull pqk00 = 0, pqk01 = 0, pqk10 = 0, pqk11 = 0;
        const ulonglong2* ki0 = (const ulonglong2*)(sk + i0 * SDK);
        const ulonglong2* ki1 = (const ulonglong2*)(sk + (i0 + 1) * SDK);
        const ulonglong2* kj0 = (const ulonglong2*)(sk + j0 * SDK);
        const ulonglong2* kj1 = (const ulonglong2*)(sk + (j0 + 1) * SDK);
        const ulonglong2* qi0 = (const ulonglong2*)(sq + i0 * SDK);
        const ulonglong2* qi1 = (const ulonglong2*)(sq + (i0 + 1) * SDK);
        #pragma unroll 8
        for (int d4 = 0; d4 < 32; d4++) {
            ulonglong2 A0 = ki0[d4], A1 = ki1[d4];
            ulonglong2 B0 = kj0[d4], B1 = kj1[d4];
            ulonglong2 C0 = qi0[d4], C1 = qi1[d4];
            fm2(pkk00, A0.x, B0.x); fm2(pkk00, A0.y, B0.y);
            fm2(pkk01, A0.x, B1.x); fm2(pkk01, A0.y, B1.y);
            fm2(pkk10, A1.x, B0.x); fm2(pkk10, A1.y, B0.y);
            fm2(pkk11, A1.x, B1.x); fm2(pkk11, A1.y, B1.y);
            fm2(pqk00, C0.x, B0.x); fm2(pqk00, C0.y, B0.y);
            fm2(pqk01, C0.x, B1.x); fm2(pqk01, C0.y, B1.y);
            fm2(pqk10, C1.x, B0.x); fm2(pqk10, C1.y, B0.y);
            fm2(pqk11, C1.x, B1.x); fm2(pqk11, C1.y, B1.y);
        }
        float2 e;
        e = upk(pkk00); float dkk00 = e.x + e.y;
        e = upk(pkk01); float dkk01 = e.x + e.y;
        e = upk(pkk10); float dkk10 = e.x + e.y;
        e = upk(pkk11); float dkk11 = e.x + e.y;
        e = upk(pqk00); float dqk00 = e.x + e.y;
        e = upk(pqk01); float dqk01 = e.x + e.y;
        e = upk(pqk10); float dqk10 = e.x + e.y;
        e = upk(pqk11); float dqk11 = e.x + e.y;
        float bi0 = sbeta[i0], bi1 = sbeta[i0 + 1];
        sA[i0 * (CC + 1) + j0]           = (i0 > j0)         ? -bi0 * dkk00 : 0.f;
        sA[i0 * (CC + 1) + j0 + 1]       = (i0 > j0 + 1)     ? -bi0 * dkk01 : 0.f;
        sA[(i0 + 1) * (CC + 1) + j0]     = (i0 + 1 > j0)     ? -bi1 * dkk10 : 0.f;
        sA[(i0 + 1) * (CC + 1) + j0 + 1] = (i0 + 1 > j0 + 1) ? -bi1 * dkk11 : 0.f;
        #define ATW(ii, jj, val) g_at2[abase + (size_t)(ii) * 32 + \
            (size_t)(((((jj) >> 2) ^ ((ii) & 7)) << 2) + ((jj) & 3))] = (val)
        ATW(i0,     j0,     (i0 >= j0)         ? dqk00 : 0.f);
        ATW(i0,     j0 + 1, (i0 >= j0 + 1)     ? dqk01 : 0.f);
        ATW(i0 + 1, j0,     (i0 + 1 >= j0)     ? dqk10 : 0.f);
        ATW(i0 + 1, j0 + 1, (i0 + 1 >= j0 + 1) ? dqk11 : 0.f);
        #undef ATW
    }
    __syncthreads();

    // forward substitution (exact reference recurrence), warp 0
    if (t < 32) {
        int lane = t;
        for (int i = 1; i < CC; i++) {
            float s = 0.f;
            if (lane < i) {
                for (int kk = lane + 1; kk < i; kk++)
                    s += sA[i * (CC + 1) + kk] * sA[kk * (CC + 1) + lane];
            }
            __syncwarp();
            if (lane < i) sA[i * (CC + 1) + lane] += s;
            __syncwarp();
        }
        sA[lane * (CC + 1) + lane] = 1.0f;
    }
    __syncthreads();

    for (int idx = t; idx < CC * CC; idx += 256) {
        int i = idx >> 5, j = idx & 31;
        sA[i * (CC + 1) + j] *= sbeta[j];
    }
    __syncthreads();

    // u = Abeta @ v (slice-blocked) ; w = Abeta @ k-hat -> g_wqT k-major cols 0..31
    {
        int p = t >> 4, dseg = t & 15;
        int i0 = 2 * p, d0 = 8 * dseg;
        ulonglong2 u0a = {0,0}, u0b = {0,0}, u1a = {0,0}, u1b = {0,0};
        ulonglong2 w0a = {0,0}, w0b = {0,0}, w1a = {0,0}, w1b = {0,0};
        #pragma unroll 4
        for (int j = 0; j < CC; j++) {
            ull A0 = pk1(sA[i0 * (CC + 1) + j]);
            ull A1 = pk1(sA[(i0 + 1) * (CC + 1) + j]);
            ulonglong2 va = *(const ulonglong2*)(sv + j * SDK + d0);
            ulonglong2 vb = *(const ulonglong2*)(sv + j * SDK + d0 + 4);
            ulonglong2 ka = *(const ulonglong2*)(sk + j * SDK + d0);
            ulonglong2 kb = *(const ulonglong2*)(sk + j * SDK + d0 + 4);
            fm2(u0a.x, A0, va.x); fm2(u0a.y, A0, va.y);
            fm2(u0b.x, A0, vb.x); fm2(u0b.y, A0, vb.y);
            fm2(u1a.x, A1, va.x); fm2(u1a.y, A1, va.y);
            fm2(u1b.x, A1, vb.x); fm2(u1b.y, A1, vb.y);
            fm2(w0a.x, A0, ka.x); fm2(w0a.y, A0, ka.y);
            fm2(w0b.x, A0, kb.x); fm2(w0b.y, A0, kb.y);
            fm2(w1a.x, A1, ka.x); fm2(w1a.y, A1, ka.y);
            fm2(w1b.x, A1, kb.x); fm2(w1b.y, A1, kb.y);
        }
        int sl = d0 >> 4, off = d0 & 15;
        size_t ub2 = (((size_t)(bh * 8 + sl)) * NCH + ch) * 512;
        *(ulonglong2*)(g_u2 + ub2 + (size_t)i0 * 16 + off)           = u0a;
        *(ulonglong2*)(g_u2 + ub2 + (size_t)i0 * 16 + off + 4)       = u0b;
        *(ulonglong2*)(g_u2 + ub2 + (size_t)(i0 + 1) * 16 + off)     = u1a;
        *(ulonglong2*)(g_u2 + ub2 + (size_t)(i0 + 1) * 16 + off + 4) = u1b;
        float w0arr[8], w1arr[8];
        float2 e;
        e = upk(w0a.x); w0arr[0] = e.x; w0arr[1] = e.y;
        e = upk(w0a.y); w0arr[2] = e.x; w0arr[3] = e.y;
        e = upk(w0b.x); w0arr[4] = e.x; w0arr[5] = e.y;
        e = upk(w0b.y); w0arr[6] = e.x; w0arr[7] = e.y;
        e = upk(w1a.x); w1arr[0] = e.x; w1arr[1] = e.y;
        e = upk(w1a.y); w1arr[2] = e.x; w1arr[3] = e.y;
        e = upk(w1b.x); w1arr[4] = e.x; w1arr[5] = e.y;
        e = upk(w1b.y); w1arr[6] = e.x; w1arr[7] = e.y;
        #pragma unroll
        for (int dd = 0; dd < 8; dd++) {
            *(float2*)(g_wqT + wqb + (size_t)(d0 + dd) * 64 + i0) =
                make_float2(w0arr[dd], w1arr[dd]);
        }
    }
}

// =====================================================================
// Phase 2: sequential scan, dv split 8x16. grid (8, BHT), 256 threads.
// 4x4 register tiles, in-warp k-split-4 + shuffle reduce.
// sS chunk-swizzled: phys_chunk = chunk ^ (((r>>2)^(r>>5)) & 3)
// buf: wqT 8192 | kR 4096 | at 1024 | u 512  (floats)
// =====================================================================
#define BUF_F   13824
#define OFF_K   8192
#define OFF_AT  12288
#define OFF_U   13312
#define TX_BYTES 55296u

__global__ __launch_bounds__(256) void phase2_kernel(
    float* __restrict__ out, float* __restrict__ Sout)
{
    extern __shared__ float sm[];
    float* sS   = sm + 4;                 // [128][16] swizzled
    float* po   = sm + 4 + 2048;          // [32][16] qS partial
    float* bufs = sm + 4 + 2048 + 512;

    const int t = threadIdx.x;
    const int slice = blockIdx.x;
    const int bh    = blockIdx.y;
    const int c0    = slice * 16;

    const int lane = t & 31, warp = t >> 5;
    const int tl = lane & 7, kg = lane >> 3;       // kg 0..3
    const int tile = warp * 8 + tl;                // 0..63
    const int tr = tile & 15, tc = tile >> 4;      // 16 x 4 tiles
    const int i0 = tr << 2;                        // output row base
    const int cb4 = tc << 2;                       // col base

    const uint32_t mb0 = s2u(sm), mb1 = mb0 + 8;

    for (int idx = t; idx < 2048; idx += 256) sS[idx] = 0.f;
    if (t == 0) { mbar_init(mb0, 1); mbar_init(mb1, 1); }
    __syncthreads();

    const size_t cb0 = (size_t)bh * NCH;
    const size_t ublk = ((size_t)(bh * 8 + slice)) * NCH;
    if (t == 0) {
        mbar_expect(mb0, TX_BYTES);
        bulkcp(s2u(bufs),           g_wqT + cb0 * 8192, 32768, mb0);
        bulkcp(s2u(bufs + OFF_K),   g_kR  + cb0 * 4096, 16384, mb0);
        bulkcp(s2u(bufs + OFF_AT),  g_at2 + cb0 * 1024, 4096, mb0);
        bulkcp(s2u(bufs + OFF_U),   g_u2  + ublk * 512, 2048, mb0);
    }

    for (int ch = 0; ch < NCH; ch++) {
        const int b = ch & 1;
        float* B  = bufs + b * BUF_F;
        float* bu = B + OFF_U;

        __syncthreads();
        if (t == 0 && ch + 1 < NCH) {
            uint32_t mb = b ? mb0 : mb1;
            float* B2 = bufs + (b ^ 1) * BUF_F;
            const size_t cb = cb0 + ch + 1;
            mbar_expect(mb, TX_BYTES);
            bulkcp(s2u(B2),          g_wqT + cb * 8192, 32768, mb);
            bulkcp(s2u(B2 + OFF_K),  g_kR  + cb * 4096, 16384, mb);
            bulkcp(s2u(B2 + OFF_AT), g_at2 + cb * 1024, 4096, mb);
            bulkcp(s2u(B2 + OFF_U),  g_u2  + (ublk + ch + 1) * 512, 2048, mb);
        }
        mbar_wait(b ? mb1 : mb0, (ch >> 1) & 1);

        // ---- P = [w;q]@S : 4x4 tile, k-split-4, swizzled S reads ----
        ull a00 = 0, a01 = 0, a10 = 0, a11 = 0, a20 = 0, a21 = 0, a30 = 0, a31 = 0;
        {
            const float* wp = B + (kg << 5) * 64 + i0;   // wqT[r][i0..i0+3]
            const float* sbase = sS + (kg << 5) * 16;
            #pragma unroll
            for (int k = 0; k < 32; k++) {
                float4 w4 = *(const float4*)(wp + k * 64);
                const int phys = ((tc ^ ((k >> 2) & 3) ^ kg) << 2);
                ulonglong2 s2 = *(const ulonglong2*)(sbase + k * 16 + phys);
                fm2(a00, pk1(w4.x), s2.x); fm2(a01, pk1(w4.x), s2.y);
                fm2(a10, pk1(w4.y), s2.x); fm2(a11, pk1(w4.y), s2.y);
                fm2(a20, pk1(w4.z), s2.x); fm2(a21, pk1(w4.z), s2.y);
                fm2(a30, pk1(w4.w), s2.x); fm2(a31, pk1(w4.w), s2.y);
            }
        }
        // butterfly reduce over kg (lane bits 3,4)
        #pragma unroll
        for (int m = 8; m <= 16; m <<= 1) {
            a00 = ad2r(a00, __shfl_xor_sync(0xffffffffu, a00, m));
            a01 = ad2r(a01, __shfl_xor_sync(0xffffffffu, a01, m));
            a10 = ad2r(a10, __shfl_xor_sync(0xffffffffu, a10, m));
            a11 = ad2r(a11, __shfl_xor_sync(0xffffffffu, a11, m));
            a20 = ad2r(a20, __shfl_xor_sync(0xffffffffu, a20, m));
            a21 = ad2r(a21, __shfl_xor_sync(0xffffffffu, a21, m));
            a30 = ad2r(a30, __shfl_xor_sync(0xffffffffu, a30, m));
            a31 = ad2r(a31, __shfl_xor_sync(0xffffffffu, a31, m));
        }
        if (kg == 0) {
            if (tr < 8) {
                // rows i0..i0+3 are w-rows: u' = u - wS, in place
                float* up = bu + i0 * 16 + cb4;
                float2 l0 = upk(a00), h0 = upk(a01);
                float2 l1 = upk(a10), h1 = upk(a11);
                float2 l2 = upk(a20), h2 = upk(a21);
                float2 l3 = upk(a30), h3 = upk(a31);
                float4 u0 = *(const float4*)(up);
                float4 u1 = *(const float4*)(up + 16);
                float4 u2 = *(const float4*)(up + 32);
                float4 u3 = *(const float4*)(up + 48);
                u0.x -= l0.x; u0.y -= l0.y; u0.z -= h0.x; u0.w -= h0.y;
                u1.x -= l1.x; u1.y -= l1.y; u1.z -= h1.x; u1.w -= h1.y;
                u2.x -= l2.x; u2.y -= l2.y; u2.z -= h2.x; u2.w -= h2.y;
                u3.x -= l3.x; u3.y -= l3.y; u3.z -= h3.x; u3.w -= h3.y;
                *(float4*)(up)      = u0;
                *(float4*)(up + 16) = u1;
                *(float4*)(up + 32) = u2;
                *(float4*)(up + 48) = u3;
            } else {
                // q-rows: stage qS into po (plain layout)
                float* pp = po + (i0 - 32) * 16 + cb4;
                float2 l0 = upk(a00), h0 = upk(a01);
                float2 l1 = upk(a10), h1 = upk(a11);
                float2 l2 = upk(a20), h2 = upk(a21);
                float2 l3 = upk(a30), h3 = upk(a31);
                *(float4*)(pp)      = make_float4(l0.x, l0.y, h0.x, h0.y);
                *(float4*)(pp + 16) = make_float4(l1.x, l1.y, h1.x, h1.y);
                *(float4*)(pp + 32) = make_float4(l2.x, l2.y, h2.x, h2.y);
                *(float4*)(pp + 48) = make_float4(l3.x, l3.y, h3.x, h3.y);
            }
        }
        __syncthreads();

        if (t < 128) {
            // ---- S += kT @ u' : 4x4 tiles over [128][16], swizzled acc ----
            const int rt = t >> 2, ct = t & 3;
            const int rb = rt << 2;
            const int physc = ((ct ^ ((rt ^ (rt >> 3)) & 3)) << 2);  // const per thread
            float* sp0 = sS + rb * 16 + physc;
            ulonglong2 s0 = *(const ulonglong2*)(sp0);
            ulonglong2 s1 = *(const ulonglong2*)(sp0 + 16);
            ulonglong2 s2v = *(const ulonglong2*)(sp0 + 32);
            ulonglong2 s3 = *(const ulonglong2*)(sp0 + 48);
            const float* kp = B + OFF_K + rb;
            const float* up2 = bu + (ct << 2);
            #pragma unroll 8
            for (int j = 0; j < 32; j++) {
                float4 k4 = *(const float4*)kp;
                ulonglong2 u2 = *(const ulonglong2*)up2;
                fm2(s0.x,  pk1(k4.x), u2.x); fm2(s0.y,  pk1(k4.x), u2.y);
                fm2(s1.x,  pk1(k4.y), u2.x); fm2(s1.y,  pk1(k4.y), u2.y);
                fm2(s2v.x, pk1(k4.z), u2.x); fm2(s2v.y, pk1(k4.z), u2.y);
                fm2(s3.x,  pk1(k4.w), u2.x); fm2(s3.y,  pk1(k4.w), u2.y);
                kp += 128; up2 += 16;
            }
            *(ulonglong2*)(sp0)      = s0;
            *(ulonglong2*)(sp0 + 16) = s1;
            *(ulonglong2*)(sp0 + 32) = s2v;
            *(ulonglong2*)(sp0 + 48) = s3;
        } else {
            // ---- o = qS + attn @ u' ----
            const int ii2 = (t - 128) >> 2, cq = t & 3;
            const int asw = ii2 & 7;
            ulonglong2 acc = *(const ulonglong2*)(po + ii2 * 16 + (cq << 2));
            const float* atr = B + OFF_AT + ii2 * 32;
            const float* Up = bu + (cq << 2);
            #pragma unroll
            for (int j4 = 0; j4 < 8; j4++) {
                float4 a4 = *(const float4*)(atr + ((j4 ^ asw) << 2));
                const float* u0p = Up + (j4 << 6);
                ulonglong2 U0 = *(const ulonglong2*)(u0p);
                ulonglong2 U1 = *(const ulonglong2*)(u0p + 16);
                ulonglong2 U2 = *(const ulonglong2*)(u0p + 32);
                ulonglong2 U3 = *(const ulonglong2*)(u0p + 48);
                fm2(acc.x, pk1(a4.x), U0.x); fm2(acc.y, pk1(a4.x), U0.y);
                fm2(acc.x, pk1(a4.y), U1.x); fm2(acc.y, pk1(a4.y), U1.y);
                fm2(acc.x, pk1(a4.z), U2.x); fm2(acc.y, pk1(a4.z), U2.y);
                fm2(acc.x, pk1(a4.w), U3.x); fm2(acc.y, pk1(a4.w), U3.y);
            }
            float2 f0 = upk(acc.x), f1 = upk(acc.y);
            size_t off = ((size_t)bh * LL + (size_t)ch * CC + ii2) * DVV + c0 + (cq << 2);
            *(float4*)(out + off) = make_float4(f0.x, f0.y, f1.x, f1.y);
        }
    }

    if (Sout != nullptr) {
        __syncthreads();
        size_t sb = (size_t)bh * DKK * DVV;
        for (int idx = t; idx < 2048; idx += 256) {
            int r = idx >> 4, c = idx & 15;
            int phys = ((((c >> 2) ^ ((r >> 2) & 3) ^ ((r >> 5) & 3)) & 3) << 2) + (c & 3);
            Sout[sb + (size_t)r * DVV + c0 + c] = sS[r * 16 + phys];
        }
    }
}

// =====================================================================
#define P1_SMEM ((3 * CC * SDK + CC * (CC + 1) + 3 * CC) * (int)sizeof(float))
#define P2_SMEM ((4 + 2048 + 512 + 2 * BUF_F) * (int)sizeof(float))

extern "C" void kernel_launch(void* const* d_in, const int* in_sizes, int n_in,
                              void* d_out, int out_size)
{
    const float* q    = (const float*)d_in[0];
    const float* k    = (const float*)d_in[1];
    const float* v    = (const float*)d_in[2];
    const float* beta = (const float*)d_in[3];
    float* out = (float*)d_out;
    float* Sout = ((size_t)out_size >= OUT_ELEMS + S_ELEMS) ? (out + OUT_ELEMS) : nullptr;

    cudaFuncSetAttribute(phase1_kernel, cudaFuncAttributeMaxDynamicSharedMemorySize, P1_SMEM);
    cudaFuncSetAttribute(phase2_kernel, cudaFuncAttributeMaxDynamicSharedMemorySize, P2_SMEM);

    phase1_kernel<<<dim3(NCH, BHT), 256, P1_SMEM>>>(q, k, v, beta);
    phase2_kernel<<<dim3(8, BHT), 256, P2_SMEM>>>(out, Sout);
}

// round 7
// speedup vs baseline: 1.8989x; 1.0564x over previous
#include <cuda_runtime.h>
#include <cuda_bf16.h>
#include <cstdint>
#include <cstddef>

#define BB   2
#define HH   8
#define LL   4096
#define DKK  128
#define DVV  128
#define CC   32
#define NCH  128
#define BHT  16
#define SDK  132

#define OUT_ELEMS  ((size_t)BB * HH * LL * DVV)
#define S_ELEMS    ((size_t)BB * HH * DKK * DVV)

typedef unsigned long long ull;

// ---------------- scratch (device globals) ----------------
// g_wqT: [bh][ch][128][64]  k-major: cols 0..31 = w rows, 32..63 = q-hat rows
// g_kR : [bh][ch][32][128]  k-hat row-major
// g_at2: [bh][ch][32][32]   masked attn, 16B chunks swizzled (j4 ^ (i&7))
// g_u2 : [bh][slice8][ch][32][16] u blocked per dv-slice
__device__ float g_wqT[(size_t)BHT * NCH * 128 * 64];
__device__ float g_kR [(size_t)BHT * NCH * 32 * 128];
__device__ float g_at2[(size_t)BHT * NCH * 32 * 32];
__device__ float g_u2 [(size_t)BHT * 8 * NCH * 32 * 16];

__device__ __forceinline__ float dot4(float4 a, float4 b) {
    return a.x * b.x + a.y * b.y + a.z * b.z + a.w * b.w;
}
__device__ __forceinline__ ull pk1(float x) {
    ull r; asm("mov.b64 %0,{%1,%1};" : "=l"(r) : "f"(x)); return r;
}
__device__ __forceinline__ void fm2(ull& a, ull b, ull c) {
    asm("fma.rn.f32x2 %0,%1,%2,%3;" : "=l"(a) : "l"(b), "l"(c), "l"(a));
}
__device__ __forceinline__ ull ad2r(ull a, ull b) {
    ull r; asm("add.rn.f32x2 %0,%1,%2;" : "=l"(r) : "l"(a), "l"(b)); return r;
}
__device__ __forceinline__ float2 upk(ull a) {
    float2 f; asm("mov.b64 {%0,%1},%2;" : "=f"(f.x), "=f"(f.y) : "l"(a)); return f;
}
__device__ __forceinline__ uint32_t s2u(const void* p) {
    return (uint32_t)__cvta_generic_to_shared(p);
}
__device__ __forceinline__ void mbar_init(uint32_t mbar, uint32_t cnt) {
    asm volatile("mbarrier.init.shared.b64 [%0], %1;" :: "r"(mbar), "r"(cnt) : "memory");
}
__device__ __forceinline__ void mbar_expect(uint32_t mbar, uint32_t bytes) {
    asm volatile("mbarrier.arrive.expect_tx.shared.b64 _, [%0], %1;" :: "r"(mbar), "r"(bytes) : "memory");
}
__device__ __forceinline__ void mbar_wait(uint32_t mbar, uint32_t parity) {
    asm volatile(
        "{\n\t.reg .pred P;\n\t"
        "W%=:\n\t"
        "mbarrier.try_wait.parity.acquire.cta.shared::cta.b64 P, [%0], %1, 0x989680;\n\t"
        "@P bra D%=;\n\t"
        "bra W%=;\n\t"
        "D%=:\n\t}"
        :: "r"(mbar), "r"(parity) : "memory");
}
__device__ __forceinline__ void bulkcp(uint32_t dst, const void* src, uint32_t bytes, uint32_t mbar) {
    asm volatile("cp.async.bulk.shared::cta.global.mbarrier::complete_tx::bytes [%0], [%1], %2, [%3];"
        :: "r"(dst), "l"(src), "r"(bytes), "r"(mbar) : "memory");
}

// =====================================================================
// Phase 1: per-chunk parallel — l2norm, tri-inverse, u, w, attn
// grid (NCH, BHT), 256 threads
// =====================================================================
__global__ __launch_bounds__(256) void phase1_kernel(
    const float* __restrict__ gq, const float* __restrict__ gk,
    const float* __restrict__ gv, const float* __restrict__ gbeta)
{
    extern __shared__ float sm[];
    float* sq    = sm;                       // CC*SDK
    float* sk    = sq + CC * SDK;
    float* sv    = sk + CC * SDK;
    float* sA    = sv + CC * SDK;            // CC*(CC+1)
    float* sbeta = sA + CC * (CC + 1);
    float* sqs   = sbeta + CC;
    float* sks   = sqs + CC;

    const int t  = threadIdx.x;
    const int ch = blockIdx.x;
    const int bh = blockIdx.y;
    const size_t gbase = ((size_t)bh * LL + (size_t)ch * CC) * DKK;

    {
        const float4* q4 = (const float4*)(gq + gbase);
        const float4* k4 = (const float4*)(gk + gbase);
        const float4* v4 = (const float4*)(gv + gbase);
        for (int idx = t; idx < CC * DKK / 4; idx += 256) {
            int r = idx >> 5, c4 = idx & 31;
            ((float4*)(sq + r * SDK))[c4] = q4[idx];
            ((float4*)(sk + r * SDK))[c4] = k4[idx];
            ((float4*)(sv + r * SDK))[c4] = v4[idx];
        }
    }
    if (t < CC) sbeta[t] = gbeta[(size_t)bh * LL + (size_t)ch * CC + t];
    __syncthreads();

    // row l2 norms
    {
        int row = t >> 3, seg = t & 7;
        const float4* qr = (const float4*)(sq + row * SDK) + seg * 4;
        const float4* kr = (const float4*)(sk + row * SDK) + seg * 4;
        float s2q = 0.f, s2k = 0.f;
        #pragma unroll
        for (int i2 = 0; i2 < 4; i2++) {
            float4 a = qr[i2]; s2q += dot4(a, a);
            float4 b = kr[i2]; s2k += dot4(b, b);
        }
        #pragma unroll
        for (int off = 4; off; off >>= 1) {
            s2q += __shfl_down_sync(0xffffffffu, s2q, off, 8);
            s2k += __shfl_down_sync(0xffffffffu, s2k, off, 8);
        }
        if (seg == 0) { sqs[row] = rsqrtf(s2q + 1e-6f); sks[row] = rsqrtf(s2k + 1e-6f); }
    }
    __syncthreads();
    {
        int row = t >> 3, seg = t & 7;
        float a = sqs[row], b = sks[row];
        float4* qr = (float4*)(sq + row * SDK) + seg * 4;
        float4* kr = (float4*)(sk + row * SDK) + seg * 4;
        #pragma unroll
        for (int i2 = 0; i2 < 4; i2++) {
            float4 x = qr[i2]; x.x *= a; x.y *= a; x.z *= a; x.w *= a; qr[i2] = x;
            float4 y = kr[i2]; y.x *= b; y.y *= b; y.z *= b; y.w *= b; kr[i2] = y;
        }
    }
    __syncthreads();

    const size_t wqb   = ((size_t)(bh * NCH + ch)) * 8192;
    const size_t krb   = ((size_t)(bh * NCH + ch)) * 4096;
    const size_t abase = ((size_t)(bh * NCH + ch)) * 1024;

    // q-hat (k-major) -> g_wqT cols 32..63
    {
        int d = t >> 1, half = t & 1, i0q = half * 16;
        #pragma unroll
        for (int ii = 0; ii < 16; ii += 4) {
            float4 a = make_float4(sq[(i0q + ii) * SDK + d], sq[(i0q + ii + 1) * SDK + d],
                                   sq[(i0q + ii + 2) * SDK + d], sq[(i0q + ii + 3) * SDK + d]);
            *(float4*)(g_wqT + wqb + (size_t)d * 64 + 32 + i0q + ii) = a;
        }
    }

    // k-hat row-major -> g_kR
    for (int idx = t; idx < 1024; idx += 256) {
        int r = idx >> 5, c4 = idx & 31;
        *(float4*)(g_kR + krb + (size_t)r * 128 + (c4 << 2)) =
            *(const float4*)(sk + r * SDK + (c4 << 2));
    }

    // dots (f32x2): A strict-lower; attn lower-incl-diag (swizzled)
    {
        int ti = t >> 4, tj = t & 15;
        int i0 = 2 * ti, j0 = 2 * tj;
        ull pkk00 = 0, pkk01 = 0, pkk10 = 0, pkk11 = 0;
        ull pqk00 = 0, pqk01 = 0, pqk10 = 0, pqk11 = 0;
        const ulonglong2* ki0 = (const ulonglong2*)(sk + i0 * SDK);
        const ulonglong2* ki1 = (const ulonglong2*)(sk + (i0 + 1) * SDK);
        const ulonglong2* kj0 = (const ulonglong2*)(sk + j0 * SDK);
        const ulonglong2* kj1 = (const ulonglong2*)(sk + (j0 + 1) * SDK);
        const ulonglong2* qi0 = (const ulonglong2*)(sq + i0 * SDK);
        const ulonglong2* qi1 = (const ulonglong2*)(sq + (i0 + 1) * SDK);
        #pragma unroll 8
        for (int d4 = 0; d4 < 32; d4++) {
            ulonglong2 A0 = ki0[d4], A1 = ki1[d4];
            ulonglong2 B0 = kj0[d4], B1 = kj1[d4];
            ulonglong2 C0 = qi0[d4], C1 = qi1[d4];
            fm2(pkk00, A0.x, B0.x); fm2(pkk00, A0.y, B0.y);
            fm2(pkk01, A0.x, B1.x); fm2(pkk01, A0.y, B1.y);
            fm2(pkk10, A1.x, B0.x); fm2(pkk10, A1.y, B0.y);
            fm2(pkk11, A1.x, B1.x); fm2(pkk11, A1.y, B1.y);
            fm2(pqk00, C0.x, B0.x); fm2(pqk00, C0.y, B0.y);
            fm2(pqk01, C0.x, B1.x); fm2(pqk01, C0.y, B1.y);
            fm2(pqk10, C1.x, B0.x); fm2(pqk10, C1.y, B0.y);
            fm2(pqk11, C1.x, B1.x); fm2(pqk11, C1.y, B1.y);
        }
        float2 e;
        e = upk(pkk00); float dkk00 = e.x + e.y;
        e = upk(pkk01); float dkk01 = e.x + e.y;
        e = upk(pkk10); float dkk10 = e.x + e.y;
        e = upk(pkk11); float dkk11 = e.x + e.y;
        e = upk(pqk00); float dqk00 = e.x + e.y;
        e = upk(pqk01); float dqk01 = e.x + e.y;
        e = upk(pqk10); float dqk10 = e.x + e.y;
        e = upk(pqk11); float dqk11 = e.x + e.y;
        float bi0 = sbeta[i0], bi1 = sbeta[i0 + 1];
        sA[i0 * (CC + 1) + j0]           = (i0 > j0)         ? -bi0 * dkk00 : 0.f;
        sA[i0 * (CC + 1) + j0 + 1]       = (i0 > j0 + 1)     ? -bi0 * dkk01 : 0.f;
        sA[(i0 + 1) * (CC + 1) + j0]     = (i0 + 1 > j0)     ? -bi1 * dkk10 : 0.f;
        sA[(i0 + 1) * (CC + 1) + j0 + 1] = (i0 + 1 > j0 + 1) ? -bi1 * dkk11 : 0.f;
        #define ATW(ii, jj, val) g_at2[abase + (size_t)(ii) * 32 + \
            (size_t)(((((jj) >> 2) ^ ((ii) & 7)) << 2) + ((jj) & 3))] = (val)
        ATW(i0,     j0,     (i0 >= j0)         ? dqk00 : 0.f);
        ATW(i0,     j0 + 1, (i0 >= j0 + 1)     ? dqk01 : 0.f);
        ATW(i0 + 1, j0,     (i0 + 1 >= j0)     ? dqk10 : 0.f);
        ATW(i0 + 1, j0 + 1, (i0 + 1 >= j0 + 1) ? dqk11 : 0.f);
        #undef ATW
    }
    __syncthreads();

    // forward substitution (exact reference recurrence), warp 0
    if (t < 32) {
        int lane = t;
        for (int i = 1; i < CC; i++) {
            float s = 0.f;
            if (lane < i) {
                for (int kk = lane + 1; kk < i; kk++)
                    s += sA[i * (CC + 1) + kk] * sA[kk * (CC + 1) + lane];
            }
            __syncwarp();
            if (lane < i) sA[i * (CC + 1) + lane] += s;
            __syncwarp();
        }
        sA[lane * (CC + 1) + lane] = 1.0f;
    }
    __syncthreads();

    for (int idx = t; idx < CC * CC; idx += 256) {
        int i = idx >> 5, j = idx & 31;
        sA[i * (CC + 1) + j] *= sbeta[j];
    }
    __syncthreads();

    // u = Abeta @ v (slice-blocked) ; w = Abeta @ k-hat -> g_wqT k-major cols 0..31
    {
        int p = t >> 4, dseg = t & 15;
        int i0 = 2 * p, d0 = 8 * dseg;
        ulonglong2 u0a = {0,0}, u0b = {0,0}, u1a = {0,0}, u1b = {0,0};
        ulonglong2 w0a = {0,0}, w0b = {0,0}, w1a = {0,0}, w1b = {0,0};
        #pragma unroll 4
        for (int j = 0; j < CC; j++) {
            ull A0 = pk1(sA[i0 * (CC + 1) + j]);
            ull A1 = pk1(sA[(i0 + 1) * (CC + 1) + j]);
            ulonglong2 va = *(const ulonglong2*)(sv + j * SDK + d0);
            ulonglong2 vb = *(const ulonglong2*)(sv + j * SDK + d0 + 4);
            ulonglong2 ka = *(const ulonglong2*)(sk + j * SDK + d0);
            ulonglong2 kb = *(const ulonglong2*)(sk + j * SDK + d0 + 4);
            fm2(u0a.x, A0, va.x); fm2(u0a.y, A0, va.y);
            fm2(u0b.x, A0, vb.x); fm2(u0b.y, A0, vb.y);
            fm2(u1a.x, A1, va.x); fm2(u1a.y, A1, va.y);
            fm2(u1b.x, A1, vb.x); fm2(u1b.y, A1, vb.y);
            fm2(w0a.x, A0, ka.x); fm2(w0a.y, A0, ka.y);
            fm2(w0b.x, A0, kb.x); fm2(w0b.y, A0, kb.y);
            fm2(w1a.x, A1, ka.x); fm2(w1a.y, A1, ka.y);
            fm2(w1b.x, A1, kb.x); fm2(w1b.y, A1, kb.y);
        }
        int sl = d0 >> 4, off = d0 & 15;
        size_t ub2 = (((size_t)(bh * 8 + sl)) * NCH + ch) * 512;
        *(ulonglong2*)(g_u2 + ub2 + (size_t)i0 * 16 + off)           = u0a;
        *(ulonglong2*)(g_u2 + ub2 + (size_t)i0 * 16 + off + 4)       = u0b;
        *(ulonglong2*)(g_u2 + ub2 + (size_t)(i0 + 1) * 16 + off)     = u1a;
        *(ulonglong2*)(g_u2 + ub2 + (size_t)(i0 + 1) * 16 + off + 4) = u1b;
        float w0arr[8], w1arr[8];
        float2 e;
        e = upk(w0a.x); w0arr[0] = e.x; w0arr[1] = e.y;
        e = upk(w0a.y); w0arr[2] = e.x; w0arr[3] = e.y;
        e = upk(w0b.x); w0arr[4] = e.x; w0arr[5] = e.y;
        e = upk(w0b.y); w0arr[6] = e.x; w0arr[7] = e.y;
        e = upk(w1a.x); w1arr[0] = e.x; w1arr[1] = e.y;
        e = upk(w1a.y); w1arr[2] = e.x; w1arr[3] = e.y;
        e = upk(w1b.x); w1arr[4] = e.x; w1arr[5] = e.y;
        e = upk(w1b.y); w1arr[6] = e.x; w1arr[7] = e.y;
        #pragma unroll
        for (int dd = 0; dd < 8; dd++) {
            *(float2*)(g_wqT + wqb + (size_t)(d0 + dd) * 64 + i0) =
                make_float2(w0arr[dd], w1arr[dd]);
        }
    }
}

// =====================================================================
// Phase 2: sequential scan, dv split 8x16. grid (8, BHT), 256 threads.
// 4x4 register tiles, in-warp k-split-4 + shuffle reduce.
// sS chunk-swizzled: phys_chunk = chunk ^ (((r>>2)^(r>>5)) & 3)
// buf: wqT 8192 | kR 4096 | at 1024 | u 512  (floats)
// =====================================================================
#define BUF_F   13824
#define OFF_K   8192
#define OFF_AT  12288
#define OFF_U   13312
#define TX_BYTES 55296u

__global__ __launch_bounds__(256) void phase2_kernel(
    float* __restrict__ out, float* __restrict__ Sout)
{
    extern __shared__ float sm[];
    float* sS   = sm + 4;                 // [128][16] swizzled
    float* po   = sm + 4 + 2048;          // [32][16] qS partial
    float* bufs = sm + 4 + 2048 + 512;

    const int t = threadIdx.x;
    const int slice = blockIdx.x;
    const int bh    = blockIdx.y;
    const int c0    = slice * 16;

    const int lane = t & 31, warp = t >> 5;
    const int tl = lane & 7, kg = lane >> 3;       // kg 0..3
    const int tile = warp * 8 + tl;                // 0..63
    const int tr = tile & 15, tc = tile >> 4;      // 16 x 4 tiles
    const int i0 = tr << 2;                        // output row base
    const int cb4 = tc << 2;                       // col base

    const uint32_t mb0 = s2u(sm), mb1 = mb0 + 8;

    for (int idx = t; idx < 2048; idx += 256) sS[idx] = 0.f;
    if (t == 0) { mbar_init(mb0, 1); mbar_init(mb1, 1); }
    __syncthreads();

    const size_t cb0 = (size_t)bh * NCH;
    const size_t ublk = ((size_t)(bh * 8 + slice)) * NCH;
    if (t == 0) {
        mbar_expect(mb0, TX_BYTES);
        bulkcp(s2u(bufs),           g_wqT + cb0 * 8192, 32768, mb0);
        bulkcp(s2u(bufs + OFF_K),   g_kR  + cb0 * 4096, 16384, mb0);
        bulkcp(s2u(bufs + OFF_AT),  g_at2 + cb0 * 1024, 4096, mb0);
        bulkcp(s2u(bufs + OFF_U),   g_u2  + ublk * 512, 2048, mb0);
    }

    for (int ch = 0; ch < NCH; ch++) {
        const int b = ch & 1;
        float* B  = bufs + b * BUF_F;
        float* bu = B + OFF_U;

        __syncthreads();
        if (t == 0 && ch + 1 < NCH) {
            uint32_t mb = b ? mb0 : mb1;
            float* B2 = bufs + (b ^ 1) * BUF_F;
            const size_t cb = cb0 + ch + 1;
            mbar_expect(mb, TX_BYTES);
            bulkcp(s2u(B2),          g_wqT + cb * 8192, 32768, mb);
            bulkcp(s2u(B2 + OFF_K),  g_kR  + cb * 4096, 16384, mb);
            bulkcp(s2u(B2 + OFF_AT), g_at2 + cb * 1024, 4096, mb);
            bulkcp(s2u(B2 + OFF_U),  g_u2  + (ublk + ch + 1) * 512, 2048, mb);
        }
        mbar_wait(b ? mb1 : mb0, (ch >> 1) & 1);

        // ---- P = [w;q]@S : 4x4 tile, k-split-4, swizzled S reads ----
        ull a00 = 0, a01 = 0, a10 = 0, a11 = 0, a20 = 0, a21 = 0, a30 = 0, a31 = 0;
        {
            const float* wp = B + (kg << 5) * 64 + i0;   // wqT[r][i0..i0+3]
            const float* sbase = sS + (kg << 5) * 16;
            #pragma unroll
            for (int k = 0; k < 32; k++) {
                float4 w4 = *(const float4*)(wp + k * 64);
                const int phys = ((tc ^ ((k >> 2) & 3) ^ kg) << 2);
                ulonglong2 s2 = *(const ulonglong2*)(sbase + k * 16 + phys);
                fm2(a00, pk1(w4.x), s2.x); fm2(a01, pk1(w4.x), s2.y);
                fm2(a10, pk1(w4.y), s2.x); fm2(a11, pk1(w4.y), s2.y);
                fm2(a20, pk1(w4.z), s2.x); fm2(a21, pk1(w4.z), s2.y);
                fm2(a30, pk1(w4.w), s2.x); fm2(a31, pk1(w4.w), s2.y);
            }
        }
        // butterfly reduce over kg (lane bits 3,4)
        #pragma unroll
        for (int m = 8; m <= 16; m <<= 1) {
            a00 = ad2r(a00, __shfl_xor_sync(0xffffffffu, a00, m));
            a01 = ad2r(a01, __shfl_xor_sync(0xffffffffu, a01, m));
            a10 = ad2r(a10, __shfl_xor_sync(0xffffffffu, a10, m));
            a11 = ad2r(a11, __shfl_xor_sync(0xffffffffu, a11, m));
            a20 = ad2r(a20, __shfl_xor_sync(0xffffffffu, a20, m));
            a21 = ad2r(a21, __shfl_xor_sync(0xffffffffu, a21, m));
            a30 = ad2r(a30, __shfl_xor_sync(0xffffffffu, a30, m));
            a31 = ad2r(a31, __shfl_xor_sync(0xffffffffu, a31, m));
        }
        if (kg == 0) {
            if (tr < 8) {
                // rows i0..i0+3 are w-rows: u' = u - wS, in place
                float* up = bu + i0 * 16 + cb4;
                float2 l0 = upk(a00), h0 = upk(a01);
                float2 l1 = upk(a10), h1 = upk(a11);
                float2 l2 = upk(a20), h2 = upk(a21);
                float2 l3 = upk(a30), h3 = upk(a31);
                float4 u0 = *(const float4*)(up);
                float4 u1 = *(const float4*)(up + 16);
                float4 u2 = *(const float4*)(up + 32);
                float4 u3 = *(const float4*)(up + 48);
                u0.x -= l0.x; u0.y -= l0.y; u0.z -= h0.x; u0.w -= h0.y;
                u1.x -= l1.x; u1.y -= l1.y; u1.z -= h1.x; u1.w -= h1.y;
                u2.x -= l2.x; u2.y -= l2.y; u2.z -= h2.x; u2.w -= h2.y;
                u3.x -= l3.x; u3.y -= l3.y; u3.z -= h3.x; u3.w -= h3.y;
                *(float4*)(up)      = u0;
                *(float4*)(up + 16) = u1;
                *(float4*)(up + 32) = u2;
                *(float4*)(up + 48) = u3;
            } else {
                // q-rows: stage qS into po (plain layout)
                float* pp = po + (i0 - 32) * 16 + cb4;
                float2 l0 = upk(a00), h0 = upk(a01);
                float2 l1 = upk(a10), h1 = upk(a11);
                float2 l2 = upk(a20), h2 = upk(a21);
                float2 l3 = upk(a30), h3 = upk(a31);
                *(float4*)(pp)      = make_float4(l0.x, l0.y, h0.x, h0.y);
                *(float4*)(pp + 16) = make_float4(l1.x, l1.y, h1.x, h1.y);
                *(float4*)(pp + 32) = make_float4(l2.x, l2.y, h2.x, h2.y);
                *(float4*)(pp + 48) = make_float4(l3.x, l3.y, h3.x, h3.y);
            }
        }
        __syncthreads();

        if (t < 128) {
            // ---- S += kT @ u' : 4x4 tiles over [128][16], swizzled acc ----
            const int rt = t >> 2, ct = t & 3;
            const int rb = rt << 2;
            const int physc = ((ct ^ ((rt ^ (rt >> 3)) & 3)) << 2);  // const per thread
            float* sp0 = sS + rb * 16 + physc;
            ulonglong2 s0 = *(const ulonglong2*)(sp0);
            ulonglong2 s1 = *(const ulonglong2*)(sp0 + 16);
            ulonglong2 s2v = *(const ulonglong2*)(sp0 + 32);
            ulonglong2 s3 = *(const ulonglong2*)(sp0 + 48);
            const float* kp = B + OFF_K + rb;
            const float* up2 = bu + (ct << 2);
            #pragma unroll 8
            for (int j = 0; j < 32; j++) {
                float4 k4 = *(const float4*)kp;
                ulonglong2 u2 = *(const ulonglong2*)up2;
                fm2(s0.x,  pk1(k4.x), u2.x); fm2(s0.y,  pk1(k4.x), u2.y);
                fm2(s1.x,  pk1(k4.y), u2.x); fm2(s1.y,  pk1(k4.y), u2.y);
                fm2(s2v.x, pk1(k4.z), u2.x); fm2(s2v.y, pk1(k4.z), u2.y);
                fm2(s3.x,  pk1(k4.w), u2.x); fm2(s3.y,  pk1(k4.w), u2.y);
                kp += 128; up2 += 16;
            }
            *(ulonglong2*)(sp0)      = s0;
            *(ulonglong2*)(sp0 + 16) = s1;
            *(ulonglong2*)(sp0 + 32) = s2v;
            *(ulonglong2*)(sp0 + 48) = s3;
        } else {
            // ---- o = qS + attn @ u' ----
            const int ii2 = (t - 128) >> 2, cq = t & 3;
            const int asw = ii2 & 7;
            ulonglong2 acc = *(const ulonglong2*)(po + ii2 * 16 + (cq << 2));
            const float* atr = B + OFF_AT + ii2 * 32;
            const float* Up = bu + (cq << 2);
            #pragma unroll
            for (int j4 = 0; j4 < 8; j4++) {
                float4 a4 = *(const float4*)(atr + ((j4 ^ asw) << 2));
                const float* u0p = Up + (j4 << 6);
                ulonglong2 U0 = *(const ulonglong2*)(u0p);
                ulonglong2 U1 = *(const ulonglong2*)(u0p + 16);
                ulonglong2 U2 = *(const ulonglong2*)(u0p + 32);
                ulonglong2 U3 = *(const ulonglong2*)(u0p + 48);
                fm2(acc.x, pk1(a4.x), U0.x); fm2(acc.y, pk1(a4.x), U0.y);
                fm2(acc.x, pk1(a4.y), U1.x); fm2(acc.y, pk1(a4.y), U1.y);
                fm2(acc.x, pk1(a4.z), U2.x); fm2(acc.y, pk1(a4.z), U2.y);
                fm2(acc.x, pk1(a4.w), U3.x); fm2(acc.y, pk1(a4.w), U3.y);
            }
            float2 f0 = upk(acc.x), f1 = upk(acc.y);
            size_t off = ((size_t)bh * LL + (size_t)ch * CC + ii2) * DVV + c0 + (cq << 2);
            *(float4*)(out + off) = make_float4(f0.x, f0.y, f1.x, f1.y);
        }
    }

    if (Sout != nullptr) {
        __syncthreads();
        size_t sb = (size_t)bh * DKK * DVV;
        for (int idx = t; idx < 2048; idx += 256) {
            int r = idx >> 4, c = idx & 15;
            int phys = ((((c >> 2) ^ ((r >> 2) & 3) ^ ((r >> 5) & 3)) & 3) << 2) + (c & 3);
            Sout[sb + (size_t)r * DVV + c0 + c] = sS[r * 16 + phys];
        }
    }
}

// =====================================================================
#define P1_SMEM ((3 * CC * SDK + CC * (CC + 1) + 3 * CC) * (int)sizeof(float))
#define P2_SMEM ((4 + 2048 + 512 + 2 * BUF_F) * (int)sizeof(float))

extern "C" void kernel_launch(void* const* d_in, const int* in_sizes, int n_in,
                              void* d_out, int out_size)
{
    const float* q    = (const float*)d_in[0];
    const float* k    = (const float*)d_in[1];
    const float* v    = (const float*)d_in[2];
    const float* beta = (const float*)d_in[3];
    float* out = (float*)d_out;
    float* Sout = ((size_t)out_size >= OUT_ELEMS + S_ELEMS) ? (out + OUT_ELEMS) : nullptr;

    cudaFuncSetAttribute(phase1_kernel, cudaFuncAttributeMaxDynamicSharedMemorySize, P1_SMEM);
    cudaFuncSetAttribute(phase2_kernel, cudaFuncAttributeMaxDynamicSharedMemorySize, P2_SMEM);

    phase1_kernel<<<dim3(NCH, BHT), 256, P1_SMEM>>>(q, k, v, beta);
    phase2_kernel<<<dim3(8, BHT), 256, P2_SMEM>>>(out, Sout);
}